// round 15
// baseline (speedup 1.0000x reference)
#include <cuda_runtime.h>
#include <cuda_fp16.h>
#include <cstdint>
#include <math.h>

#define BATCH 4
#define SEQ   2048
#define HID   2048

// ---------------- static device scratch (no allocations allowed) ----------------
static __device__ float  g_scores[(size_t)BATCH * SEQ * SEQ];   // 64 MB
static __device__ __half g_Qh[(size_t)BATCH * SEQ * HID];
static __device__ __half g_Kh[(size_t)BATCH * SEQ * HID];
static __device__ __half g_Vh[(size_t)BATCH * HID * SEQ];       // transposed [b][n][k]
static __device__ __half g_Ph[(size_t)BATCH * SEQ * SEQ];

// ---------------- helpers ----------------
__device__ __forceinline__ uint32_t smem_to_u32(const void* p) {
    uint32_t a;
    asm("{ .reg .u64 t; cvta.to.shared.u64 t, %1; cvt.u32.u64 %0, t; }" : "=r"(a) : "l"(p));
    return a;
}

#define LDSM_X4(r0, r1, r2, r3, addr) \
    asm volatile("ldmatrix.sync.aligned.m8n8.x4.shared.b16 {%0,%1,%2,%3}, [%4];" \
        : "=r"(r0), "=r"(r1), "=r"(r2), "=r"(r3) : "r"(addr))

#define MMA16816(d, a, b0v, b1v) \
    asm volatile("mma.sync.aligned.m16n8k16.row.col.f32.f16.f16.f32 " \
        "{%0,%1,%2,%3},{%4,%5,%6,%7},{%8,%9},{%0,%1,%2,%3};" \
        : "+f"((d)[0]), "+f"((d)[1]), "+f"((d)[2]), "+f"((d)[3]) \
        : "r"((a)[0]), "r"((a)[1]), "r"((a)[2]), "r"((a)[3]), "r"(b0v), "r"(b1v))

#define CP_ASYNC16(dst, src) \
    asm volatile("cp.async.cg.shared.global [%0], [%1], 16;" :: "r"(dst), "l"(src))
#define CP_COMMIT() asm volatile("cp.async.commit_group;" ::: "memory")
#define CP_WAIT0()  asm volatile("cp.async.wait_group 0;" ::: "memory")

// ---------------- conversion kernels ----------------
// sel: 0 -> g_Qh, 1 -> g_Kh  (destination resolved in device code)
__global__ __launch_bounds__(256) void kconv(const float4* __restrict__ src, int sel)
{
    __half* dst = sel ? g_Kh : g_Qh;
    size_t i = (size_t)blockIdx.x * 256 + threadIdx.x;
    float4 v = src[i];
    __half2* d2 = reinterpret_cast<__half2*>(dst + i * 4);
    d2[0] = __floats2half2_rn(v.x, v.y);
    d2[1] = __floats2half2_rn(v.z, v.w);
}

// V [b][k][n] -> Vh transposed [b][n][k]
__global__ __launch_bounds__(256) void ktransV(const float* __restrict__ V)
{
    __shared__ float tile[32][33];
    const int b  = blockIdx.z;
    const int n0 = blockIdx.x * 32;
    const int k0 = blockIdx.y * 32;
    const int tx = threadIdx.x, ty = threadIdx.y;   // (32, 8)
    const float* Vb = V + (size_t)b * SEQ * HID;
    #pragma unroll
    for (int j = 0; j < 4; j++)
        tile[ty + 8 * j][tx] = Vb[(size_t)(k0 + ty + 8 * j) * HID + n0 + tx];
    __syncthreads();
    __half* Hh = g_Vh + (size_t)b * HID * SEQ;
    #pragma unroll
    for (int j = 0; j < 4; j++) {
        float x = tile[tx][ty + 8 * j];
        size_t o = (size_t)(n0 + ty + 8 * j) * SEQ + k0 + tx;
        Hh[o] = __float2half_rn(x);
    }
}

// ---------------- softmax (fp32 scores -> fp16 weights), vectorized ----------------
__global__ __launch_bounds__(256) void ksoftmax()
{
    const size_t row = blockIdx.x;
    const float4* p4 = reinterpret_cast<const float4*>(g_scores + row * SEQ);
    __half* ph = g_Ph + row * SEQ;
    const int tid = threadIdx.x, lane = tid & 31, warp = tid >> 5;
    __shared__ float red[8];

    float4 v[2];
    v[0] = p4[tid];
    v[1] = p4[tid + 256];
    float m = fmaxf(fmaxf(v[0].x, v[0].y), fmaxf(v[0].z, v[0].w));
    m = fmaxf(m, fmaxf(fmaxf(v[1].x, v[1].y), fmaxf(v[1].z, v[1].w)));
    #pragma unroll
    for (int off = 16; off > 0; off >>= 1) m = fmaxf(m, __shfl_xor_sync(~0u, m, off));
    if (lane == 0) red[warp] = m;
    __syncthreads();
    float mall = red[0];
    #pragma unroll
    for (int w = 1; w < 8; w++) mall = fmaxf(mall, red[w]);
    __syncthreads();

    float s = 0.f;
    #pragma unroll
    for (int i = 0; i < 2; i++) {
        v[i].x = __expf(v[i].x - mall); s += v[i].x;
        v[i].y = __expf(v[i].y - mall); s += v[i].y;
        v[i].z = __expf(v[i].z - mall); s += v[i].z;
        v[i].w = __expf(v[i].w - mall); s += v[i].w;
    }
    #pragma unroll
    for (int off = 16; off > 0; off >>= 1) s += __shfl_xor_sync(~0u, s, off);
    if (lane == 0) red[warp] = s;
    __syncthreads();
    float tot = 0.f;
    #pragma unroll
    for (int w = 0; w < 8; w++) tot += red[w];
    float inv = 1.f / tot;

    #pragma unroll
    for (int i = 0; i < 2; i++) {
        __half2 h0 = __floats2half2_rn(v[i].x * inv, v[i].y * inv);
        __half2 h1 = __floats2half2_rn(v[i].z * inv, v[i].w * inv);
        uint2 pk;
        pk.x = *reinterpret_cast<uint32_t*>(&h0);
        pk.y = *reinterpret_cast<uint32_t*>(&h1);
        *reinterpret_cast<uint2*>(ph + (tid + i * 256) * 4) = pk;
    }
}

// ---------------- mma.sync GEMM:  C[m][n] = sum_k A[m][k]*B[n][k]  (fp16) ----------------
// CTA tile 128x256, warp tile 64x64 (2x4 warp grid), KC=32, 3-stage cp.async.
// phase 0: A = Qh, B = Kh, out = g_scores, epilogue *= scale*sigmoid(span[n])
// phase 1: A = Ph, B = Vh, out = O
#define BM    128
#define BN    256
#define KC    32
#define NCH   (HID / KC)          // 64
#define ROWB  80                  // 32 halves (64B) + 16B pad
#define ABUF  (BM * ROWB)         // 10240
#define BBUF  (BN * ROWB)         // 20480
#define STAGE (ABUF + BBUF)       // 30720
#define NSTG  3
#define SM_GATE (NSTG * STAGE)    // 92160
#define SM_TOT  (SM_GATE + 1536)

__global__ __launch_bounds__(256, 1) void kgemm(int phase, const float* __restrict__ span,
                                                float* __restrict__ outp)
{
    extern __shared__ char smem[];
    const uint32_t su = smem_to_u32(smem);
    const int tid  = threadIdx.x;
    const int lane = tid & 31;
    const int wid  = tid >> 5;
    const int wm   = wid >> 2;       // 0..1, m offset = wm*64
    const int wn   = wid & 3;        // 0..3, n offset = wn*64
    const int b  = blockIdx.z;
    const int m0 = blockIdx.y * BM;
    const int n0 = blockIdx.x * BN;

    const __half* Ahp = (phase ? g_Ph : g_Qh) + (size_t)b * SEQ * HID + (size_t)m0 * HID;
    const __half* Bhp = (phase ? g_Vh : g_Kh) + (size_t)b * SEQ * HID + (size_t)n0 * HID;
    float* Cb = phase ? (outp + (size_t)b * SEQ * HID) : (g_scores + (size_t)b * SEQ * SEQ);

    float* gate_s = reinterpret_cast<float*>(smem + SM_GATE);
    {
        if (phase == 0) {
            const float scale = 0.02209708691207961f;   // 1/sqrt(2048)
            float sv = span[n0 + tid];
            gate_s[tid] = scale / (1.f + __expf(-sv));
        } else gate_s[tid] = 1.0f;
    }

    // A: 128 rows x 4 segs (512), B: 256 rows x 4 segs (1024) -> 6 cp.async/thread
    auto load_stage = [&](int chunk, int s) {
        const int k0 = chunk * KC;
        uint32_t abase = su + (uint32_t)(s * STAGE);
        #pragma unroll
        for (int i = 0; i < 2; i++) {
            int idx = tid + i * 256;          // 0..511
            int row = idx >> 2, seg = idx & 3;
            CP_ASYNC16(abase + row * ROWB + seg * 16,
                       Ahp + (size_t)row * HID + k0 + seg * 8);
        }
        uint32_t bbase = abase + ABUF;
        #pragma unroll
        for (int i = 0; i < 4; i++) {
            int idx = tid + i * 256;          // 0..1023
            int row = idx >> 2, seg = idx & 3;
            CP_ASYNC16(bbase + row * ROWB + seg * 16,
                       Bhp + (size_t)row * HID + k0 + seg * 8);
        }
        CP_COMMIT();
    };

    float acc[4][8][4];
    #pragma unroll
    for (int mi = 0; mi < 4; mi++)
        #pragma unroll
        for (int ni = 0; ni < 8; ni++)
            #pragma unroll
            for (int r = 0; r < 4; r++) acc[mi][ni][r] = 0.f;

    // double-buffered fragments (buffer index compile-time)
    uint32_t ahf[2][4][4], bhf[2][4][4];

    // ldmatrix lane-address components
    const int a_row  = wm * 64 + (lane & 15);                      // + mi*16
    const uint32_t a_koff = (uint32_t)((lane >> 4) * 16);
    const int b_row  = wn * 64 + ((lane >> 4) * 8) + (lane & 7);   // + p*16
    const uint32_t b_koff = (uint32_t)(((lane >> 3) & 1) * 16);

    #define LDSM_SLICE(stg, ks, bf) do {                                                \
        const uint32_t _base = su + (uint32_t)((stg) * STAGE);                          \
        const uint32_t _ko = (uint32_t)((ks) * 32);                                     \
        _Pragma("unroll")                                                               \
        for (int p = 0; p < 4; p++) {                                                   \
            uint32_t bd = _base + ABUF + (uint32_t)((b_row + p * 16) * ROWB) + _ko + b_koff; \
            LDSM_X4(bhf[bf][p][0], bhf[bf][p][1], bhf[bf][p][2], bhf[bf][p][3], bd);    \
        }                                                                               \
        _Pragma("unroll")                                                               \
        for (int mi = 0; mi < 4; mi++) {                                                \
            uint32_t ad = _base + (uint32_t)((a_row + mi * 16) * ROWB) + _ko + a_koff;  \
            LDSM_X4(ahf[bf][mi][0], ahf[bf][mi][1], ahf[bf][mi][2], ahf[bf][mi][3], ad);\
        }                                                                               \
    } while (0)

    #define MMA_SLICE(bf) do {                                                          \
        _Pragma("unroll")                                                               \
        for (int mi = 0; mi < 4; mi++)                                                  \
            _Pragma("unroll")                                                           \
            for (int ni = 0; ni < 8; ni++)                                              \
                MMA16816(acc[mi][ni], ahf[bf][mi],                                      \
                         bhf[bf][ni >> 1][(ni & 1) * 2],                                \
                         bhf[bf][ni >> 1][(ni & 1) * 2 + 1]);                           \
    } while (0)

    // prologue: 2 stages in flight
    load_stage(0, 0);
    load_stage(1, 1);

    int s = 0;          // stage of chunk c
    for (int c = 0; c < NCH; c++) {
        // All issued loads complete -> chunks c AND c+1 resident.
        CP_WAIT0();
        __syncthreads();                  // visibility + protect overwritten stage
        if (c + 2 < NCH) {
            int s2 = s + 2; if (s2 >= NSTG) s2 -= NSTG;
            load_stage(c + 2, s2);
        }

        if (c == 0) LDSM_SLICE(0, 0, 0);  // prime once

        LDSM_SLICE(s, 1, 1);              // slice 1 of this chunk
        MMA_SLICE(0);
        if (c + 1 < NCH) {                // cross-chunk prefetch (c+1 resident)
            int s1 = s + 1; if (s1 >= NSTG) s1 -= NSTG;
            LDSM_SLICE(s1, 0, 0);
        }
        MMA_SLICE(1);

        if (++s == NSTG) s = 0;
    }

    // epilogue
    #pragma unroll
    for (int mi = 0; mi < 4; mi++) {
        int r0 = m0 + wm * 64 + mi * 16 + (lane >> 2);
        #pragma unroll
        for (int ni = 0; ni < 8; ni++) {
            int cloc = wn * 64 + ni * 8 + (lane & 3) * 2;
            float g0 = gate_s[cloc], g1 = gate_s[cloc + 1];
            float2 v0 = make_float2(acc[mi][ni][0] * g0, acc[mi][ni][1] * g1);
            float2 v1 = make_float2(acc[mi][ni][2] * g0, acc[mi][ni][3] * g1);
            *reinterpret_cast<float2*>(&Cb[(size_t)r0 * 2048 + n0 + cloc]) = v0;
            *reinterpret_cast<float2*>(&Cb[(size_t)(r0 + 8) * 2048 + n0 + cloc]) = v1;
        }
    }
}

// -------------------------------------------------------------------------
extern "C" void kernel_launch(void* const* d_in, const int* in_sizes, int n_in,
                              void* d_out, int out_size)
{
    const float* Q    = (const float*)d_in[0];
    const float* K    = (const float*)d_in[1];
    const float* V    = (const float*)d_in[2];
    const float* span = (const float*)d_in[3];
    float* O = (float*)d_out;

    cudaFuncSetAttribute(kgemm, cudaFuncAttributeMaxDynamicSharedMemorySize, SM_TOT);

    const int n4 = (BATCH * SEQ * HID) / 4;          // float4 count
    kconv<<<n4 / 256, 256>>>((const float4*)Q, 0);
    kconv<<<n4 / 256, 256>>>((const float4*)K, 1);
    ktransV<<<dim3(HID / 32, SEQ / 32, BATCH), dim3(32, 8)>>>(V);

    dim3 gridG(SEQ / BN, SEQ / BM, BATCH);
    kgemm<<<gridG, 256, SM_TOT>>>(0, span, nullptr);
    ksoftmax<<<BATCH * SEQ, 256>>>();
    kgemm<<<gridG, 256, SM_TOT>>>(1, nullptr, O);
}

// round 16
// speedup vs baseline: 1.2740x; 1.2740x over previous
#include <cuda_runtime.h>
#include <cuda_fp16.h>
#include <cstdint>
#include <math.h>

#define BATCH 4
#define SEQ   2048
#define HID   2048

// ---------------- static device scratch (no allocations allowed) ----------------
static __device__ float  g_scores[(size_t)BATCH * SEQ * SEQ];   // 64 MB
static __device__ __half g_Qh[(size_t)BATCH * SEQ * HID];
static __device__ __half g_Kh[(size_t)BATCH * SEQ * HID];
static __device__ __half g_Vh[(size_t)BATCH * HID * SEQ];       // transposed [b][n][k]
static __device__ __half g_Ph[(size_t)BATCH * SEQ * SEQ];

// ---------------- helpers ----------------
__device__ __forceinline__ uint32_t smem_to_u32(const void* p) {
    uint32_t a;
    asm("{ .reg .u64 t; cvta.to.shared.u64 t, %1; cvt.u32.u64 %0, t; }" : "=r"(a) : "l"(p));
    return a;
}

#define LDSM_X4(r0, r1, r2, r3, addr) \
    asm volatile("ldmatrix.sync.aligned.m8n8.x4.shared.b16 {%0,%1,%2,%3}, [%4];" \
        : "=r"(r0), "=r"(r1), "=r"(r2), "=r"(r3) : "r"(addr))

#define MMA16816(d, a, b0v, b1v) \
    asm volatile("mma.sync.aligned.m16n8k16.row.col.f32.f16.f16.f32 " \
        "{%0,%1,%2,%3},{%4,%5,%6,%7},{%8,%9},{%0,%1,%2,%3};" \
        : "+f"((d)[0]), "+f"((d)[1]), "+f"((d)[2]), "+f"((d)[3]) \
        : "r"((a)[0]), "r"((a)[1]), "r"((a)[2]), "r"((a)[3]), "r"(b0v), "r"(b1v))

#define CP_ASYNC16(dst, src) \
    asm volatile("cp.async.cg.shared.global [%0], [%1], 16;" :: "r"(dst), "l"(src))
#define CP_COMMIT() asm volatile("cp.async.commit_group;" ::: "memory")
#define CP_WAIT0()  asm volatile("cp.async.wait_group 0;" ::: "memory")

// ---------------- combined Q/K fp16 conversion (blockIdx.y selects) ----------------
__global__ __launch_bounds__(256) void kconv2(const float4* __restrict__ Q,
                                              const float4* __restrict__ K)
{
    const float4* src = blockIdx.y ? K : Q;
    __half* dst = blockIdx.y ? g_Kh : g_Qh;
    size_t i = (size_t)blockIdx.x * 256 + threadIdx.x;
    float4 v = src[i];
    __half2* d2 = reinterpret_cast<__half2*>(dst + i * 4);
    d2[0] = __floats2half2_rn(v.x, v.y);
    d2[1] = __floats2half2_rn(v.z, v.w);
}

// ---------------- softmax (fp32 scores -> fp16 weights), vectorized ----------------
__global__ __launch_bounds__(256) void ksoftmax()
{
    const size_t row = blockIdx.x;
    const float4* p4 = reinterpret_cast<const float4*>(g_scores + row * SEQ);
    __half* ph = g_Ph + row * SEQ;
    const int tid = threadIdx.x, lane = tid & 31, warp = tid >> 5;
    __shared__ float red[8];

    float4 v[2];
    v[0] = p4[tid];
    v[1] = p4[tid + 256];
    float m = fmaxf(fmaxf(v[0].x, v[0].y), fmaxf(v[0].z, v[0].w));
    m = fmaxf(m, fmaxf(fmaxf(v[1].x, v[1].y), fmaxf(v[1].z, v[1].w)));
    #pragma unroll
    for (int off = 16; off > 0; off >>= 1) m = fmaxf(m, __shfl_xor_sync(~0u, m, off));
    if (lane == 0) red[warp] = m;
    __syncthreads();
    float mall = red[0];
    #pragma unroll
    for (int w = 1; w < 8; w++) mall = fmaxf(mall, red[w]);
    __syncthreads();

    float s = 0.f;
    #pragma unroll
    for (int i = 0; i < 2; i++) {
        v[i].x = __expf(v[i].x - mall); s += v[i].x;
        v[i].y = __expf(v[i].y - mall); s += v[i].y;
        v[i].z = __expf(v[i].z - mall); s += v[i].z;
        v[i].w = __expf(v[i].w - mall); s += v[i].w;
    }
    #pragma unroll
    for (int off = 16; off > 0; off >>= 1) s += __shfl_xor_sync(~0u, s, off);
    if (lane == 0) red[warp] = s;
    __syncthreads();
    float tot = 0.f;
    #pragma unroll
    for (int w = 0; w < 8; w++) tot += red[w];
    float inv = 1.f / tot;

    #pragma unroll
    for (int i = 0; i < 2; i++) {
        __half2 h0 = __floats2half2_rn(v[i].x * inv, v[i].y * inv);
        __half2 h1 = __floats2half2_rn(v[i].z * inv, v[i].w * inv);
        uint2 pk;
        pk.x = *reinterpret_cast<uint32_t*>(&h0);
        pk.y = *reinterpret_cast<uint32_t*>(&h1);
        *reinterpret_cast<uint2*>(ph + (tid + i * 256) * 4) = pk;
    }
}

// ---------------- mma.sync GEMM (R13 config) + tail-fused V transpose ----------------
// phase 0: blocks [0,1024)  GEMM  A=Qh B=Kh -> g_scores (*gate)
//          blocks [1024,2048) V-transpose f32 [b][k][n] -> fp16 Vh [b][n][k]
// phase 1: blocks [0,1024)  GEMM  A=Ph B=Vh -> O
#define KC    64
#define NCH   (HID / KC)          // 32
#define ROWB  144                 // 64 halves (128B) + 16B pad
#define BUF   (128 * ROWB)        // 18432
#define STAGE (2 * BUF)           // 36864 : Ah, Bh
#define NSTG  3
#define SM_GATE (NSTG * STAGE)    // 110592
#define SM_TOT  (SM_GATE + 512)
#define NGEMM 1024

__global__ __launch_bounds__(256, 2) void kgemm(int phase, const float* __restrict__ span,
                                                const float* __restrict__ Vp,
                                                float* __restrict__ outp)
{
    extern __shared__ char smem[];
    const int tid = threadIdx.x;
    const int bid = blockIdx.x;

    // ---------- tail blocks of phase 0: V transpose (128x128 f32 tile) ----------
    if (phase == 0 && bid >= NGEMM) {
        const int tv  = bid - NGEMM;
        const int b   = tv >> 8;
        const int rem = tv & 255;
        const int n0  = (rem & 15) * 128;
        const int k0  = (rem >> 4) * 128;
        float (*tile)[129] = reinterpret_cast<float(*)[129]>(smem);
        const float* Vb = Vp + (size_t)b * SEQ * HID;
        #pragma unroll
        for (int it = 0; it < 16; it++) {
            int idx = tid + it * 256;          // 0..4095 float4s
            int row = idx >> 5, c4 = (idx & 31) * 4;
            float4 v = *reinterpret_cast<const float4*>(
                Vb + (size_t)(k0 + row) * HID + n0 + c4);
            tile[row][c4 + 0] = v.x; tile[row][c4 + 1] = v.y;
            tile[row][c4 + 2] = v.z; tile[row][c4 + 3] = v.w;
        }
        __syncthreads();
        __half* Hh = g_Vh + (size_t)b * HID * SEQ;
        #pragma unroll
        for (int it = 0; it < 32; it++) {
            int idx = tid + it * 256;          // 0..8191 half2s
            int nn = idx >> 6, kp = (idx & 63) * 2;
            __half2 h = __floats2half2_rn(tile[kp][nn], tile[kp + 1][nn]);
            *reinterpret_cast<__half2*>(Hh + (size_t)(n0 + nn) * SEQ + k0 + kp) = h;
        }
        return;
    }

    // ---------- GEMM path (identical to R13) ----------
    const uint32_t su = smem_to_u32(smem);
    const int lane = tid & 31;
    const int wid  = tid >> 5;
    const int wm   = wid >> 2;       // 0..1, m offset = wm*64
    const int wn   = wid & 3;        // 0..3, n offset = wn*32
    const int b  = bid >> 8;
    const int rem = bid & 255;
    const int m0 = (rem >> 4) * 128;
    const int n0 = (rem & 15) * 128;

    const __half* Ahp = (phase ? g_Ph : g_Qh) + (size_t)b * SEQ * HID + (size_t)m0 * HID;
    const __half* Bhp = (phase ? g_Vh : g_Kh) + (size_t)b * SEQ * HID + (size_t)n0 * HID;
    float* Cb = phase ? (outp + (size_t)b * SEQ * HID) : (g_scores + (size_t)b * SEQ * SEQ);

    float* gate_s = reinterpret_cast<float*>(smem + SM_GATE);
    if (tid < 128) {
        if (phase == 0) {
            const float scale = 0.02209708691207961f;   // 1/sqrt(2048)
            float sv = span[n0 + tid];
            gate_s[tid] = scale / (1.f + __expf(-sv));
        } else gate_s[tid] = 1.0f;
    }

    auto load_stage = [&](int chunk, int s) {
        const int k0 = chunk * KC;
        uint32_t abase = su + (uint32_t)(s * STAGE);
        #pragma unroll
        for (int i = 0; i < 4; i++) {
            int idx = tid + i * 256;          // 0..1023
            int row = idx >> 3, seg = idx & 7;
            CP_ASYNC16(abase + row * ROWB + seg * 16,
                       Ahp + (size_t)row * HID + k0 + seg * 8);
        }
        uint32_t bbase = abase + BUF;
        #pragma unroll
        for (int i = 0; i < 4; i++) {
            int idx = tid + i * 256;
            int row = idx >> 3, seg = idx & 7;
            CP_ASYNC16(bbase + row * ROWB + seg * 16,
                       Bhp + (size_t)row * HID + k0 + seg * 8);
        }
        CP_COMMIT();
    };

    float acc[4][4][4];
    #pragma unroll
    for (int mi = 0; mi < 4; mi++)
        #pragma unroll
        for (int ni = 0; ni < 4; ni++)
            #pragma unroll
            for (int r = 0; r < 4; r++) acc[mi][ni][r] = 0.f;

    uint32_t ahf[2][4][4], bhf[2][2][4];

    const int a_row  = wm * 64 + (lane & 15);                      // + mi*16
    const uint32_t a_koff = (uint32_t)((lane >> 4) * 16);
    const int b_row  = wn * 32 + ((lane >> 4) * 8) + (lane & 7);   // + p*16
    const uint32_t b_koff = (uint32_t)(((lane >> 3) & 1) * 16);

    #define LDSM_SLICE(stg, ks, bf) do {                                                \
        const uint32_t _base = su + (uint32_t)((stg) * STAGE);                          \
        const uint32_t _ko = (uint32_t)((ks) * 32);                                     \
        _Pragma("unroll")                                                               \
        for (int p = 0; p < 2; p++) {                                                   \
            uint32_t bd = _base + BUF + (uint32_t)((b_row + p * 16) * ROWB) + _ko + b_koff; \
            LDSM_X4(bhf[bf][p][0], bhf[bf][p][1], bhf[bf][p][2], bhf[bf][p][3], bd);    \
        }                                                                               \
        _Pragma("unroll")                                                               \
        for (int mi = 0; mi < 4; mi++) {                                                \
            uint32_t ad = _base + (uint32_t)((a_row + mi * 16) * ROWB) + _ko + a_koff;  \
            LDSM_X4(ahf[bf][mi][0], ahf[bf][mi][1], ahf[bf][mi][2], ahf[bf][mi][3], ad);\
        }                                                                               \
    } while (0)

    #define MMA_SLICE(bf) do {                                                          \
        _Pragma("unroll")                                                               \
        for (int mi = 0; mi < 4; mi++)                                                  \
            _Pragma("unroll")                                                           \
            for (int ni = 0; ni < 4; ni++)                                              \
                MMA16816(acc[mi][ni], ahf[bf][mi],                                      \
                         bhf[bf][ni >> 1][(ni & 1) * 2],                                \
                         bhf[bf][ni >> 1][(ni & 1) * 2 + 1]);                           \
    } while (0)

    // prologue: 2 stages in flight
    load_stage(0, 0);
    load_stage(1, 1);

    int s = 0;          // stage of chunk c
    for (int c = 0; c < NCH; c++) {
        CP_WAIT0();                       // chunks c and c+1 resident
        __syncthreads();                  // visibility + protect overwritten stage
        if (c + 2 < NCH) {
            int s2 = s + 2; if (s2 >= NSTG) s2 -= NSTG;
            load_stage(c + 2, s2);
        }

        if (c == 0) LDSM_SLICE(0, 0, 0);  // prime once

        LDSM_SLICE(s, 1, 1);
        MMA_SLICE(0);
        LDSM_SLICE(s, 2, 0);
        MMA_SLICE(1);
        LDSM_SLICE(s, 3, 1);
        MMA_SLICE(0);
        if (c + 1 < NCH) {                // cross-chunk prefetch (c+1 resident)
            int s1 = s + 1; if (s1 >= NSTG) s1 -= NSTG;
            LDSM_SLICE(s1, 0, 0);
        }
        MMA_SLICE(1);

        if (++s == NSTG) s = 0;
    }

    // epilogue
    #pragma unroll
    for (int mi = 0; mi < 4; mi++) {
        int r0 = m0 + wm * 64 + mi * 16 + (lane >> 2);
        #pragma unroll
        for (int ni = 0; ni < 4; ni++) {
            int cloc = wn * 32 + ni * 8 + (lane & 3) * 2;
            float g0 = gate_s[cloc], g1 = gate_s[cloc + 1];
            float2 v0 = make_float2(acc[mi][ni][0] * g0, acc[mi][ni][1] * g1);
            float2 v1 = make_float2(acc[mi][ni][2] * g0, acc[mi][ni][3] * g1);
            *reinterpret_cast<float2*>(&Cb[(size_t)r0 * 2048 + n0 + cloc]) = v0;
            *reinterpret_cast<float2*>(&Cb[(size_t)(r0 + 8) * 2048 + n0 + cloc]) = v1;
        }
    }
}

// -------------------------------------------------------------------------
extern "C" void kernel_launch(void* const* d_in, const int* in_sizes, int n_in,
                              void* d_out, int out_size)
{
    const float* Q    = (const float*)d_in[0];
    const float* K    = (const float*)d_in[1];
    const float* V    = (const float*)d_in[2];
    const float* span = (const float*)d_in[3];
    float* O = (float*)d_out;

    cudaFuncSetAttribute(kgemm, cudaFuncAttributeMaxDynamicSharedMemorySize, SM_TOT);

    const int n4 = (BATCH * SEQ * HID) / 4;          // float4 count
    kconv2<<<dim3(n4 / 256, 2), 256>>>((const float4*)Q, (const float4*)K);

    // phase 0: 1024 GEMM blocks + 1024 V-transpose blocks in the tail wave
    kgemm<<<2 * NGEMM, 256, SM_TOT>>>(0, span, V, nullptr);
    ksoftmax<<<BATCH * SEQ, 256>>>();
    kgemm<<<NGEMM, 256, SM_TOT>>>(1, span, V, O);
}